// round 4
// baseline (speedup 1.0000x reference)
#include <cuda_runtime.h>

// Fused NeRF positional-encoding + 27x32 MLP + 32x1 head, fp32.
// R3: 4 points/thread (two f32x2 pairs) as in R2, but occupancy-repaired:
// __launch_bounds__(128,3) (3 blocks/SM = 12 warps) + unroll-2 j-loop to
// shrink the register footprint below the cap without spilling.

typedef unsigned long long u64;

#define TPB 128
#define NIN 27
#define HID 32

__device__ __forceinline__ u64 pack2(float a, float b) {
    u64 r; asm("mov.b64 %0, {%1,%2};" : "=l"(r) : "f"(a), "f"(b)); return r;
}
__device__ __forceinline__ void unpack2(u64 v, float& a, float& b) {
    asm("mov.b64 {%0,%1}, %2;" : "=f"(a), "=f"(b) : "l"(v));
}
__device__ __forceinline__ u64 fma2(u64 a, u64 b, u64 c) {
    u64 d; asm("fma.rn.f32x2 %0, %1, %2, %3;" : "=l"(d) : "l"(a), "l"(b), "l"(c)); return d;
}
__device__ __forceinline__ u64 mul2(u64 a, u64 b) {
    u64 d; asm("mul.rn.f32x2 %0, %1, %2;" : "=l"(d) : "l"(a), "l"(b)); return d;
}
#define K2(v) pack2((v), (v))

// Packed sincos: Cody-Waite pi/2 reduction + minimax polys, branch-free
// quadrant fixup. FMA-pipe dominant, fast-math-immune, ~1e-7 for |arg|<1e4.
__device__ __forceinline__ void sincos2(float a0, float a1, u64& s_out, u64& c_out) {
    const float TWO_OVER_PI = 0.63661977236758134308f;
    float j0 = rintf(a0 * TWO_OVER_PI);
    float j1 = rintf(a1 * TWO_OVER_PI);
    int i0 = (int)j0, i1 = (int)j1;
    u64 j2 = pack2(j0, j1);
    u64 r2 = fma2(j2, K2(-1.5707962513e+00f), pack2(a0, a1));
    r2 = fma2(j2, K2(-7.5497894159e-08f), r2);
    r2 = fma2(j2, K2(-5.3903029534e-15f), r2);
    u64 z = mul2(r2, r2);
    u64 p = fma2(z, K2(-1.9515295891e-04f), K2(8.3321608736e-03f));
    p = fma2(p, z, K2(-1.6666654611e-01f));
    u64 rz = mul2(r2, z);
    u64 s = fma2(p, rz, r2);
    u64 q = fma2(z, K2(2.4433157442e-05f), K2(-1.3887316255e-03f));
    q = fma2(q, z, K2(4.1666645683e-02f));
    q = fma2(q, z, K2(-0.5f));
    u64 c = fma2(q, z, K2(1.0f));

    float s0, s1, c0, c1;
    unpack2(s, s0, s1); unpack2(c, c0, c1);
    // quadrant (k mod 4): swap sin/cos if k odd; sign via bit xor.
    float ss0 = (i0 & 1) ? c0 : s0;
    float cs0 = (i0 & 1) ? s0 : c0;
    float ss1 = (i1 & 1) ? c1 : s1;
    float cs1 = (i1 & 1) ? s1 : c1;
    unsigned sg0 = (unsigned)(i0 & 2) << 30, cg0 = (unsigned)((i0 + 1) & 2) << 30;
    unsigned sg1 = (unsigned)(i1 & 2) << 30, cg1 = (unsigned)((i1 + 1) & 2) << 30;
    ss0 = __int_as_float(__float_as_int(ss0) ^ sg0);
    cs0 = __int_as_float(__float_as_int(cs0) ^ cg0);
    ss1 = __int_as_float(__float_as_int(ss1) ^ sg1);
    cs1 = __int_as_float(__float_as_int(cs1) ^ cg1);
    s_out = pack2(ss0, ss1);
    c_out = pack2(cs0, cs1);
}

// Build the 27 packed features for a point pair into tf[].
__device__ __forceinline__ void encode_pair(
    float x0, float y0, float z0, float x1, float y1, float z1, u64* tf)
{
    const float f1 = exp2f(3.3333333333333335f);
    const float f2 = exp2f(6.666666666666667f);
    tf[0] = pack2(x0, x1);
    tf[1] = pack2(y0, y1);
    tf[2] = pack2(z0, z1);
    float fv;
    fv = 1.0f;
    sincos2(x0 * fv, x1 * fv, tf[3 + 0], tf[3 + 3]);
    sincos2(y0 * fv, y1 * fv, tf[3 + 1], tf[3 + 4]);
    sincos2(z0 * fv, z1 * fv, tf[3 + 2], tf[3 + 5]);
    fv = f1;
    sincos2(x0 * fv, x1 * fv, tf[9 + 0], tf[9 + 3]);
    sincos2(y0 * fv, y1 * fv, tf[9 + 1], tf[9 + 4]);
    sincos2(z0 * fv, z1 * fv, tf[9 + 2], tf[9 + 5]);
    fv = f2;
    sincos2(x0 * fv, x1 * fv, tf[15 + 0], tf[15 + 3]);
    sincos2(y0 * fv, y1 * fv, tf[15 + 1], tf[15 + 4]);
    sincos2(z0 * fv, z1 * fv, tf[15 + 2], tf[15 + 5]);
    fv = 1024.0f;
    sincos2(x0 * fv, x1 * fv, tf[21 + 0], tf[21 + 3]);
    sincos2(y0 * fv, y1 * fv, tf[21 + 1], tf[21 + 4]);
    sincos2(z0 * fv, z1 * fv, tf[21 + 2], tf[21 + 5]);
}

__global__ void __launch_bounds__(TPB, 3) nerf_fused_kernel(
    const float* __restrict__ x,
    const float* __restrict__ W1,
    const float* __restrict__ b1,
    const float* __restrict__ W2,
    const float* __restrict__ b2,
    float* __restrict__ out, int N)
{
    __shared__ u64 sW1[NIN * HID];   // duplicated (w,w) pairs
    __shared__ u64 sB1[HID];
    __shared__ u64 sW2[HID];
    __shared__ float sB2;

    for (int k = threadIdx.x; k < NIN * HID; k += TPB) {
        float w = W1[k];
        sW1[k] = pack2(w, w);
    }
    if (threadIdx.x < HID) {
        float v = b1[threadIdx.x]; sB1[threadIdx.x] = pack2(v, v);
        float w = W2[threadIdx.x]; sW2[threadIdx.x] = pack2(w, w);
    }
    if (threadIdx.x == 0) sB2 = b2[0];
    __syncthreads();

    long long t = (long long)blockIdx.x * TPB + threadIdx.x;
    long long p = 4LL * t;               // first of 4 points
    if (p >= N) return;
    bool full = (p + 3 < N);

    float c0x, c0y, c0z, c1x, c1y, c1z, c2x, c2y, c2z, c3x, c3y, c3z;
    if (full) {
        const float4* xv = (const float4*)x;    // 4 points = 12 floats = 3 float4
        float4 a = xv[3 * t];
        float4 bq = xv[3 * t + 1];
        float4 cq = xv[3 * t + 2];
        c0x = a.x;  c0y = a.y;  c0z = a.z;
        c1x = a.w;  c1y = bq.x; c1z = bq.y;
        c2x = bq.z; c2y = bq.w; c2z = cq.x;
        c3x = cq.y; c3y = cq.z; c3z = cq.w;
    } else {
        long long m = N - 1;
        long long p0 = p, p1 = p + 1 > m ? m : p + 1, p2 = p + 2 > m ? m : p + 2, p3 = p + 3 > m ? m : p + 3;
        c0x = x[p0*3]; c0y = x[p0*3+1]; c0z = x[p0*3+2];
        c1x = x[p1*3]; c1y = x[p1*3+1]; c1z = x[p1*3+2];
        c2x = x[p2*3]; c2y = x[p2*3+1]; c2z = x[p2*3+2];
        c3x = x[p3*3]; c3y = x[p3*3+1]; c3z = x[p3*3+2];
    }

    u64 tfA[NIN], tfB[NIN];
    encode_pair(c0x, c0y, c0z, c1x, c1y, c1z, tfA);
    encode_pair(c2x, c2y, c2z, c3x, c3y, c3z, tfB);

    // MLP: one broadcast LDS.64 weight feeds 2 packed FMAs (4 MACs).
    // Unroll 2 (not 4): 4 independent FMA chains is enough ILP; keeps the
    // compiler's LDS-prefetch window (register cost) small.
    u64 accA = K2(0.0f), accB = K2(0.0f);
    #pragma unroll 2
    for (int j = 0; j < HID; j++) {
        u64 bj = sB1[j];
        u64 hA = bj, hB = bj;
        #pragma unroll
        for (int i = 0; i < NIN; i++) {
            u64 w = sW1[i * HID + j];
            hA = fma2(tfA[i], w, hA);
            hB = fma2(tfB[i], w, hB);
        }
        float a0, a1, b0v, b1v;
        unpack2(hA, a0, a1); unpack2(hB, b0v, b1v);
        a0 = fmaxf(a0, 0.0f); a1 = fmaxf(a1, 0.0f);
        b0v = fmaxf(b0v, 0.0f); b1v = fmaxf(b1v, 0.0f);
        u64 w2 = sW2[j];
        accA = fma2(pack2(a0, a1), w2, accA);
        accB = fma2(pack2(b0v, b1v), w2, accB);
    }

    float o0, o1, o2, o3;
    unpack2(accA, o0, o1); unpack2(accB, o2, o3);
    float bb = sB2;
    o0 = fmaxf(o0 + bb, 0.0f);
    o1 = fmaxf(o1 + bb, 0.0f);
    o2 = fmaxf(o2 + bb, 0.0f);
    o3 = fmaxf(o3 + bb, 0.0f);
    if (full) {
        ((float4*)out)[t] = make_float4(o0, o1, o2, o3);
    } else {
        long long m = N;
        if (p     < m) out[p]     = o0;
        if (p + 1 < m) out[p + 1] = o1;
        if (p + 2 < m) out[p + 2] = o2;
        if (p + 3 < m) out[p + 3] = o3;
    }
}

extern "C" void kernel_launch(void* const* d_in, const int* in_sizes, int n_in,
                              void* d_out, int out_size) {
    const float* x  = (const float*)d_in[0];
    const float* W1 = (const float*)d_in[1];
    const float* b1 = (const float*)d_in[2];
    const float* W2 = (const float*)d_in[3];
    const float* b2 = (const float*)d_in[4];
    float* out = (float*)d_out;

    int N = in_sizes[0] / 3;
    long long quads = (N + 3) / 4;
    int blocks = (int)((quads + TPB - 1) / TPB);
    nerf_fused_kernel<<<blocks, TPB>>>(x, W1, b1, W2, b2, out, N);
}

// round 6
// speedup vs baseline: 1.5358x; 1.5358x over previous
#include <cuda_runtime.h>
#include <cuda_bf16.h>
#include <cstdint>

// Fused NeRF: packed-FMA sincos encoding + layer1 via mma.sync.m16n8k16 bf16
// (2-way bf16 split, 3 combos for fp32-grade accuracy) + fp32 relu/W2 epilogue.
// Base-sm_100 compatible (no tcgen05): HMMA + ldmatrix only.

typedef unsigned long long u64;

#define TPB 128
#define ITER 8
#define NIN 27
#define HID 32

// ---------------- packed f32x2 math ----------------
__device__ __forceinline__ u64 pack2(float a, float b) {
    u64 r; asm("mov.b64 %0, {%1,%2};" : "=l"(r) : "f"(a), "f"(b)); return r;
}
__device__ __forceinline__ void unpack2(u64 v, float& a, float& b) {
    asm("mov.b64 {%0,%1}, %2;" : "=f"(a), "=f"(b) : "l"(v));
}
__device__ __forceinline__ u64 fma2(u64 a, u64 b, u64 c) {
    u64 d; asm("fma.rn.f32x2 %0, %1, %2, %3;" : "=l"(d) : "l"(a), "l"(b), "l"(c)); return d;
}
__device__ __forceinline__ u64 mul2(u64 a, u64 b) {
    u64 d; asm("mul.rn.f32x2 %0, %1, %2;" : "=l"(d) : "l"(a), "l"(b)); return d;
}
#define K2(v) pack2((v), (v))
#define CVT_BF16X2(result, lo, hi) \
    asm("cvt.rn.satfinite.bf16x2.f32 %0, %1, %2;" : "=r"(result) : "f"(hi), "f"(lo))

__device__ __forceinline__ uint32_t smem_u32(const void* p) {
    uint32_t a; asm("{ .reg .u64 t; cvta.to.shared.u64 t, %1; cvt.u32.u64 %0, t; }" : "=r"(a) : "l"(p));
    return a;
}
__device__ __forceinline__ void ldmatrix_x4(uint32_t& r0, uint32_t& r1, uint32_t& r2, uint32_t& r3, uint32_t addr) {
    asm volatile("ldmatrix.sync.aligned.m8n8.x4.shared.b16 {%0,%1,%2,%3}, [%4];"
                 : "=r"(r0), "=r"(r1), "=r"(r2), "=r"(r3) : "r"(addr));
}
__device__ __forceinline__ void ldmatrix_x2(uint32_t& r0, uint32_t& r1, uint32_t addr) {
    asm volatile("ldmatrix.sync.aligned.m8n8.x2.shared.b16 {%0,%1}, [%2];"
                 : "=r"(r0), "=r"(r1) : "r"(addr));
}
__device__ __forceinline__ void mma16816(float* c, const uint32_t* a, uint32_t b0, uint32_t b1) {
    asm volatile("mma.sync.aligned.m16n8k16.row.col.f32.bf16.bf16.f32 "
                 "{%0,%1,%2,%3},{%4,%5,%6,%7},{%8,%9},{%0,%1,%2,%3};"
                 : "+f"(c[0]), "+f"(c[1]), "+f"(c[2]), "+f"(c[3])
                 : "r"(a[0]), "r"(a[1]), "r"(a[2]), "r"(a[3]), "r"(b0), "r"(b1));
}

// Packed sincos (2 independent args): Cody-Waite pi/2 reduction + minimax
// polys, branch-free quadrant fixup. ~1e-7 abs for |arg|<1e4.
__device__ __forceinline__ void sincos2(float a0, float a1, u64& s_out, u64& c_out) {
    const float TWO_OVER_PI = 0.63661977236758134308f;
    float j0 = rintf(a0 * TWO_OVER_PI);
    float j1 = rintf(a1 * TWO_OVER_PI);
    int i0 = (int)j0, i1 = (int)j1;
    u64 j2 = pack2(j0, j1);
    u64 r2 = fma2(j2, K2(-1.5707962513e+00f), pack2(a0, a1));
    r2 = fma2(j2, K2(-7.5497894159e-08f), r2);
    r2 = fma2(j2, K2(-5.3903029534e-15f), r2);
    u64 z = mul2(r2, r2);
    u64 p = fma2(z, K2(-1.9515295891e-04f), K2(8.3321608736e-03f));
    p = fma2(p, z, K2(-1.6666654611e-01f));
    u64 rz = mul2(r2, z);
    u64 s = fma2(p, rz, r2);
    u64 q = fma2(z, K2(2.4433157442e-05f), K2(-1.3887316255e-03f));
    q = fma2(q, z, K2(4.1666645683e-02f));
    q = fma2(q, z, K2(-0.5f));
    u64 c = fma2(q, z, K2(1.0f));
    float s0, s1, c0, c1;
    unpack2(s, s0, s1); unpack2(c, c0, c1);
    float ss0 = (i0 & 1) ? c0 : s0;
    float cs0 = (i0 & 1) ? s0 : c0;
    float ss1 = (i1 & 1) ? c1 : s1;
    float cs1 = (i1 & 1) ? s1 : c1;
    unsigned sg0 = (unsigned)(i0 & 2) << 30, cg0 = (unsigned)((i0 + 1) & 2) << 30;
    unsigned sg1 = (unsigned)(i1 & 2) << 30, cg1 = (unsigned)((i1 + 1) & 2) << 30;
    ss0 = __int_as_float(__float_as_int(ss0) ^ sg0);
    cs0 = __int_as_float(__float_as_int(cs0) ^ cg0);
    ss1 = __int_as_float(__float_as_int(ss1) ^ sg1);
    cs1 = __int_as_float(__float_as_int(cs1) ^ cg1);
    s_out = pack2(ss0, ss1);
    c_out = pack2(cs0, cs1);
}

// Shared layout: rows padded to 80B (20 u32) so ldmatrix row addresses hit
// distinct bank groups (conflict-free).
#define ROWU 20

__global__ void __launch_bounds__(TPB) nerf_hmma_kernel(
    const float* __restrict__ x,
    const float* __restrict__ W1,
    const float* __restrict__ b1,
    const float* __restrict__ W2,
    const float* __restrict__ b2,
    float* __restrict__ out, long long N)
{
    __shared__ __align__(16) uint32_t sWTH[HID * ROWU];      // W1^T hi  [n][k] bf16
    __shared__ __align__(16) uint32_t sWTM[HID * ROWU];      // W1^T mid
    __shared__ __align__(16) uint32_t sFH[4][32 * ROWU];     // features hi, per warp
    __shared__ __align__(16) uint32_t sFM[4][32 * ROWU];     // features mid
    __shared__ float2 sBW[HID];                              // (b1, W2)

    int tid = threadIdx.x;
    int lane = tid & 31;
    int w = tid >> 5;
    int t4 = lane & 3, g4 = lane >> 2;

    // Build W1^T bf16 hi/mid tiles (k >= NIN zero-padded)
    {
        __nv_bfloat16* wh = (__nv_bfloat16*)sWTH;
        __nv_bfloat16* wm = (__nv_bfloat16*)sWTM;
        for (int idx = tid; idx < HID * 32; idx += TPB) {
            int n = idx >> 5, k = idx & 31;
            float v = (k < NIN) ? W1[k * HID + n] : 0.0f;
            __nv_bfloat16 bh = __float2bfloat16(v);
            float rm = v - __bfloat162float(bh);
            wh[n * (ROWU * 2) + k] = bh;
            wm[n * (ROWU * 2) + k] = __float2bfloat16(rm);
        }
    }
    if (tid < HID) sBW[tid] = make_float2(b1[tid], W2[tid]);
    __syncthreads();

    // Load B fragments once: [nc][ks][reg] for hi and mid
    uint32_t bh[4][2][2], bm[4][2][2];
    {
        int l16 = lane & 15;
        int rN = l16 & 7;
        int inM1 = l16 >> 3;
        uint32_t baseH = smem_u32(sWTH);
        uint32_t baseM = smem_u32(sWTM);
        #pragma unroll
        for (int nc = 0; nc < 4; nc++) {
            #pragma unroll
            for (int ks = 0; ks < 2; ks++) {
                uint32_t off = (uint32_t)((nc * 8 + rN) * 80 + (ks * 16 + inM1 * 8) * 2);
                ldmatrix_x2(bh[nc][ks][0], bh[nc][ks][1], baseH + off);
                ldmatrix_x2(bm[nc][ks][0], bm[nc][ks][1], baseM + off);
            }
        }
    }
    float2 bw0[4], bw1[4];
    #pragma unroll
    for (int nc = 0; nc < 4; nc++) {
        bw0[nc] = sBW[nc * 8 + 2 * t4];
        bw1[nc] = sBW[nc * 8 + 2 * t4 + 1];
    }
    float b2v = b2[0];

    uint32_t fhB = smem_u32(&sFH[w][0]);
    uint32_t fmB = smem_u32(&sFM[w][0]);
    const float f1 = exp2f(3.3333333333333335f);
    const float f2 = exp2f(6.666666666666667f);

    for (int it = 0; it < ITER; it++) {
        long long pbase = ((long long)blockIdx.x * ITER + it) * (4LL * 32) + w * 32;
        long long p = pbase + lane;

        float xv = 0.0f, yv = 0.0f, zv = 0.0f;
        if (p < N) { xv = x[p * 3]; yv = x[p * 3 + 1]; zv = x[p * 3 + 2]; }

        // 27 features: [x,y,z, per-band sin(xyz), cos(xyz)]
        float f[28];
        f[0] = xv; f[1] = yv; f[2] = zv; f[27] = 0.0f;
        {
            u64 s, c;
            sincos2(xv, yv, s, c);            unpack2(s, f[3],  f[4]);  unpack2(c, f[6],  f[7]);
            sincos2(zv, xv * f1, s, c);       unpack2(s, f[5],  f[9]);  unpack2(c, f[8],  f[12]);
            sincos2(yv * f1, zv * f1, s, c);  unpack2(s, f[10], f[11]); unpack2(c, f[13], f[14]);
            sincos2(xv * f2, yv * f2, s, c);  unpack2(s, f[15], f[16]); unpack2(c, f[18], f[19]);
            sincos2(zv * f2, xv * 1024.0f, s, c); unpack2(s, f[17], f[21]); unpack2(c, f[20], f[24]);
            sincos2(yv * 1024.0f, zv * 1024.0f, s, c); unpack2(s, f[22], f[23]); unpack2(c, f[25], f[26]);
        }

        // bf16 hi/mid split, packed pairs
        uint32_t hi[16], mi[16];
        #pragma unroll
        for (int c2 = 0; c2 < 14; c2++) {
            float a = f[2 * c2], b = f[2 * c2 + 1];
            uint32_t hp; CVT_BF16X2(hp, a, b);
            float ha = __uint_as_float(hp << 16);
            float hb = __uint_as_float(hp & 0xFFFF0000u);
            uint32_t mp; CVT_BF16X2(mp, a - ha, b - hb);
            hi[c2] = hp; mi[c2] = mp;
        }
        hi[14] = hi[15] = mi[14] = mi[15] = 0;

        // Store this point's feature row (row = lane), 80B stride
        {
            uint32_t* rh = &sFH[w][lane * ROWU];
            uint32_t* rm = &sFM[w][lane * ROWU];
            *(uint4*)(rh + 0)  = make_uint4(hi[0], hi[1], hi[2], hi[3]);
            *(uint4*)(rh + 4)  = make_uint4(hi[4], hi[5], hi[6], hi[7]);
            *(uint4*)(rh + 8)  = make_uint4(hi[8], hi[9], hi[10], hi[11]);
            *(uint4*)(rh + 12) = make_uint4(hi[12], hi[13], hi[14], hi[15]);
            *(uint4*)(rm + 0)  = make_uint4(mi[0], mi[1], mi[2], mi[3]);
            *(uint4*)(rm + 4)  = make_uint4(mi[4], mi[5], mi[6], mi[7]);
            *(uint4*)(rm + 8)  = make_uint4(mi[8], mi[9], mi[10], mi[11]);
            *(uint4*)(rm + 12) = make_uint4(mi[12], mi[13], mi[14], mi[15]);
        }
        __syncwarp();

        // Two m16 tiles of 16 points each
        #pragma unroll
        for (int mt = 0; mt < 2; mt++) {
            int rowl = mt * 16 + (lane & 15);
            uint32_t aoff = (uint32_t)(rowl * 80 + ((lane >> 4) & 1) * 16);
            uint32_t ah[8], am[8];
            ldmatrix_x4(ah[0], ah[1], ah[2], ah[3], fhB + aoff);
            ldmatrix_x4(ah[4], ah[5], ah[6], ah[7], fhB + aoff + 32);
            ldmatrix_x4(am[0], am[1], am[2], am[3], fmB + aoff);
            ldmatrix_x4(am[4], am[5], am[6], am[7], fmB + aoff + 32);

            float C[4][4];
            #pragma unroll
            for (int nc = 0; nc < 4; nc++)
                { C[nc][0] = C[nc][1] = C[nc][2] = C[nc][3] = 0.0f; }

            #pragma unroll
            for (int nc = 0; nc < 4; nc++) {
                #pragma unroll
                for (int ks = 0; ks < 2; ks++) {
                    mma16816(C[nc], ah + ks * 4, bh[nc][ks][0], bh[nc][ks][1]);
                    mma16816(C[nc], ah + ks * 4, bm[nc][ks][0], bm[nc][ks][1]);
                    mma16816(C[nc], am + ks * 4, bh[nc][ks][0], bh[nc][ks][1]);
                }
            }

            // Epilogue: relu(h + b1) dot W2, reduced across the 4-lane group
            float s0 = 0.0f, s1 = 0.0f;
            #pragma unroll
            for (int nc = 0; nc < 4; nc++) {
                s0 = fmaf(fmaxf(C[nc][0] + bw0[nc].x, 0.0f), bw0[nc].y, s0);
                s0 = fmaf(fmaxf(C[nc][1] + bw1[nc].x, 0.0f), bw1[nc].y, s0);
                s1 = fmaf(fmaxf(C[nc][2] + bw0[nc].x, 0.0f), bw0[nc].y, s1);
                s1 = fmaf(fmaxf(C[nc][3] + bw1[nc].x, 0.0f), bw1[nc].y, s1);
            }
            s0 += __shfl_xor_sync(0xFFFFFFFFu, s0, 1);
            s0 += __shfl_xor_sync(0xFFFFFFFFu, s0, 2);
            s1 += __shfl_xor_sync(0xFFFFFFFFu, s1, 1);
            s1 += __shfl_xor_sync(0xFFFFFFFFu, s1, 2);
            if (t4 == 0) {
                long long q0 = pbase + mt * 16 + g4;
                long long q1 = q0 + 8;
                if (q0 < N) out[q0] = fmaxf(s0 + b2v, 0.0f);
                if (q1 < N) out[q1] = fmaxf(s1 + b2v, 0.0f);
            }
        }
        __syncwarp();
    }
}

extern "C" void kernel_launch(void* const* d_in, const int* in_sizes, int n_in,
                              void* d_out, int out_size) {
    const float* x  = (const float*)d_in[0];
    const float* W1 = (const float*)d_in[1];
    const float* b1 = (const float*)d_in[2];
    const float* W2 = (const float*)d_in[3];
    const float* b2 = (const float*)d_in[4];
    float* out = (float*)d_out;

    long long N = in_sizes[0] / 3;
    long long per_block = (long long)ITER * TPB;   // 1024 points per block
    int blocks = (int)((N + per_block - 1) / per_block);
    nerf_hmma_kernel<<<blocks, TPB>>>(x, W1, b1, W2, b2, out, N);
}

// round 7
// speedup vs baseline: 1.6978x; 1.1055x over previous
#include <cuda_runtime.h>
#include <cuda_bf16.h>
#include <cstdint>

// Fused NeRF: packed-FMA sincos encoding + layer1 via mma.sync.m16n8k16 bf16
// (2-way bf16 split, 3 combos) + fp32 relu/W2 epilogue. Base-sm_100 (no tcgen05).
// R7: pi-based range reduction (sign-only fixup, no selects — ALU was 32%),
// dropped 3rd Cody-Waite term, coordinate prefetch pipeline.

typedef unsigned long long u64;

#define TPB 128
#define ITER 8
#define NIN 27
#define HID 32

// ---------------- packed f32x2 math ----------------
__device__ __forceinline__ u64 pack2(float a, float b) {
    u64 r; asm("mov.b64 %0, {%1,%2};" : "=l"(r) : "f"(a), "f"(b)); return r;
}
__device__ __forceinline__ void unpack2(u64 v, float& a, float& b) {
    asm("mov.b64 {%0,%1}, %2;" : "=f"(a), "=f"(b) : "l"(v));
}
__device__ __forceinline__ u64 fma2(u64 a, u64 b, u64 c) {
    u64 d; asm("fma.rn.f32x2 %0, %1, %2, %3;" : "=l"(d) : "l"(a), "l"(b), "l"(c)); return d;
}
__device__ __forceinline__ u64 mul2(u64 a, u64 b) {
    u64 d; asm("mul.rn.f32x2 %0, %1, %2;" : "=l"(d) : "l"(a), "l"(b)); return d;
}
#define K2(v) pack2((v), (v))
#define CVT_BF16X2(result, lo, hi) \
    asm("cvt.rn.satfinite.bf16x2.f32 %0, %1, %2;" : "=r"(result) : "f"(hi), "f"(lo))

__device__ __forceinline__ uint32_t smem_u32(const void* p) {
    uint32_t a; asm("{ .reg .u64 t; cvta.to.shared.u64 t, %1; cvt.u32.u64 %0, t; }" : "=r"(a) : "l"(p));
    return a;
}
__device__ __forceinline__ void ldmatrix_x4(uint32_t& r0, uint32_t& r1, uint32_t& r2, uint32_t& r3, uint32_t addr) {
    asm volatile("ldmatrix.sync.aligned.m8n8.x4.shared.b16 {%0,%1,%2,%3}, [%4];"
                 : "=r"(r0), "=r"(r1), "=r"(r2), "=r"(r3) : "r"(addr));
}
__device__ __forceinline__ void ldmatrix_x2(uint32_t& r0, uint32_t& r1, uint32_t addr) {
    asm volatile("ldmatrix.sync.aligned.m8n8.x2.shared.b16 {%0,%1}, [%2];"
                 : "=r"(r0), "=r"(r1) : "r"(addr));
}
__device__ __forceinline__ void mma16816(float* c, const uint32_t* a, uint32_t b0, uint32_t b1) {
    asm volatile("mma.sync.aligned.m16n8k16.row.col.f32.bf16.bf16.f32 "
                 "{%0,%1,%2,%3},{%4,%5,%6,%7},{%8,%9},{%0,%1,%2,%3};"
                 : "+f"(c[0]), "+f"(c[1]), "+f"(c[2]), "+f"(c[3])
                 : "r"(a[0]), "r"(a[1]), "r"(a[2]), "r"(a[3]), "r"(b0), "r"(b1));
}

// Packed sincos, pi-based reduction: theta = j*pi + r, r in [-pi/2, pi/2].
// sin(theta) = (-1)^j sin(r), cos(theta) = (-1)^j cos(r): single sign mask,
// no swap/select. Taylor deg-11 sin / deg-12 cos (remainder <= 6e-8 at pi/2).
// Valid to ~1e-7 for |arg| < ~6e3 (j <= ~2000, 2-term Cody-Waite).
__device__ __forceinline__ void sincos2(float a0, float a1, u64& s_out, u64& c_out) {
    const float INV_PI = 0.31830988618379067f;
    const float PI_HI = 3.14159274101257324f;   // fp32(pi)
    const float PI_LO = -8.74227765735e-08f;    // pi - fp32(pi)
    float j0 = rintf(a0 * INV_PI);
    float j1 = rintf(a1 * INV_PI);
    int i0 = (int)j0, i1 = (int)j1;
    u64 j2 = pack2(j0, j1);
    u64 r2 = fma2(j2, K2(-PI_HI), pack2(a0, a1));
    r2 = fma2(j2, K2(-PI_LO), r2);
    u64 z = mul2(r2, r2);
    // sin(r) = r + r*z*(S1 + z*(S2 + z*(S3 + z*S4)))
    u64 p = fma2(z, K2(2.7557319e-06f), K2(-1.9841270e-04f));
    p = fma2(p, z, K2(8.3333333e-03f));
    p = fma2(p, z, K2(-1.6666667e-01f));
    u64 rz = mul2(r2, z);
    u64 s = fma2(p, rz, r2);
    // cos(r) = 1 + z*(-0.5 + z*(C2 + z*(C3 + z*(C4 + z*C5))))
    u64 q = fma2(z, K2(-2.7557319e-07f), K2(2.4801587e-05f));
    q = fma2(q, z, K2(-1.3888889e-03f));
    q = fma2(q, z, K2(4.1666668e-02f));
    q = fma2(q, z, K2(-0.5f));
    u64 c = fma2(q, z, K2(1.0f));
    // sign mask: bit0 of j -> sign bit, same mask for sin and cos
    unsigned m0 = (unsigned)(i0 << 31);
    unsigned m1 = (unsigned)(i1 << 31);
    u64 mask; asm("mov.b64 %0, {%1,%2};" : "=l"(mask) : "r"(m0), "r"(m1));
    s_out = s ^ mask;
    c_out = c ^ mask;
}

// Shared rows padded to 80B (20 u32): conflict-free ldmatrix.
#define ROWU 20

__global__ void __launch_bounds__(TPB) nerf_hmma_kernel(
    const float* __restrict__ x,
    const float* __restrict__ W1,
    const float* __restrict__ b1,
    const float* __restrict__ W2,
    const float* __restrict__ b2,
    float* __restrict__ out, long long N)
{
    __shared__ __align__(16) uint32_t sWTH[HID * ROWU];      // W1^T hi  [n][k] bf16
    __shared__ __align__(16) uint32_t sWTM[HID * ROWU];      // W1^T mid
    __shared__ __align__(16) uint32_t sFH[4][32 * ROWU];     // features hi, per warp
    __shared__ __align__(16) uint32_t sFM[4][32 * ROWU];     // features mid
    __shared__ float2 sBW[HID];                              // (b1, W2)

    int tid = threadIdx.x;
    int lane = tid & 31;
    int w = tid >> 5;
    int t4 = lane & 3, g4 = lane >> 2;

    // Build W1^T bf16 hi/mid tiles (k >= NIN zero-padded)
    {
        __nv_bfloat16* wh = (__nv_bfloat16*)sWTH;
        __nv_bfloat16* wm = (__nv_bfloat16*)sWTM;
        for (int idx = tid; idx < HID * 32; idx += TPB) {
            int n = idx >> 5, k = idx & 31;
            float v = (k < NIN) ? W1[k * HID + n] : 0.0f;
            __nv_bfloat16 bh = __float2bfloat16(v);
            float rm = v - __bfloat162float(bh);
            wh[n * (ROWU * 2) + k] = bh;
            wm[n * (ROWU * 2) + k] = __float2bfloat16(rm);
        }
    }
    if (tid < HID) sBW[tid] = make_float2(b1[tid], W2[tid]);
    __syncthreads();

    // Load B fragments once: [nc][ks][reg] for hi and mid
    uint32_t bh[4][2][2], bm[4][2][2];
    {
        int l16 = lane & 15;
        int rN = l16 & 7;
        int inM1 = l16 >> 3;
        uint32_t baseH = smem_u32(sWTH);
        uint32_t baseM = smem_u32(sWTM);
        #pragma unroll
        for (int nc = 0; nc < 4; nc++) {
            #pragma unroll
            for (int ks = 0; ks < 2; ks++) {
                uint32_t off = (uint32_t)((nc * 8 + rN) * 80 + (ks * 16 + inM1 * 8) * 2);
                ldmatrix_x2(bh[nc][ks][0], bh[nc][ks][1], baseH + off);
                ldmatrix_x2(bm[nc][ks][0], bm[nc][ks][1], baseM + off);
            }
        }
    }
    float2 bw0[4], bw1[4];
    #pragma unroll
    for (int nc = 0; nc < 4; nc++) {
        bw0[nc] = sBW[nc * 8 + 2 * t4];
        bw1[nc] = sBW[nc * 8 + 2 * t4 + 1];
    }
    float b2v = b2[0];

    uint32_t fhB = smem_u32(&sFH[w][0]);
    uint32_t fmB = smem_u32(&sFM[w][0]);
    const float f1 = exp2f(3.3333333333333335f);
    const float f2 = exp2f(6.666666666666667f);

    long long warp_base = (long long)blockIdx.x * ITER * (4LL * 32) + w * 32;

    // Prefetch iter-0 coords
    float nx = 0.0f, ny = 0.0f, nz = 0.0f;
    {
        long long p = warp_base + lane;
        if (p < N) { nx = x[p * 3]; ny = x[p * 3 + 1]; nz = x[p * 3 + 2]; }
    }

    for (int it = 0; it < ITER; it++) {
        long long pbase = warp_base + (long long)it * (4LL * 32);
        float xv = nx, yv = ny, zv = nz;

        // kick off next iter's loads early (hide DRAM latency behind compute)
        if (it + 1 < ITER) {
            long long pn = pbase + 128 + lane;
            nx = ny = nz = 0.0f;
            if (pn < N) { nx = x[pn * 3]; ny = x[pn * 3 + 1]; nz = x[pn * 3 + 2]; }
        }

        // 27 features: [x,y,z, per-band sin(xyz), cos(xyz)]
        float f[28];
        f[0] = xv; f[1] = yv; f[2] = zv; f[27] = 0.0f;
        {
            u64 s, c;
            sincos2(xv, yv, s, c);            unpack2(s, f[3],  f[4]);  unpack2(c, f[6],  f[7]);
            sincos2(zv, xv * f1, s, c);       unpack2(s, f[5],  f[9]);  unpack2(c, f[8],  f[12]);
            sincos2(yv * f1, zv * f1, s, c);  unpack2(s, f[10], f[11]); unpack2(c, f[13], f[14]);
            sincos2(xv * f2, yv * f2, s, c);  unpack2(s, f[15], f[16]); unpack2(c, f[18], f[19]);
            sincos2(zv * f2, xv * 1024.0f, s, c); unpack2(s, f[17], f[21]); unpack2(c, f[20], f[24]);
            sincos2(yv * 1024.0f, zv * 1024.0f, s, c); unpack2(s, f[22], f[23]); unpack2(c, f[25], f[26]);
        }

        // bf16 hi/mid split, packed pairs
        uint32_t hi[16], mi[16];
        #pragma unroll
        for (int c2 = 0; c2 < 14; c2++) {
            float a = f[2 * c2], b = f[2 * c2 + 1];
            uint32_t hp; CVT_BF16X2(hp, a, b);
            float ha = __uint_as_float(hp << 16);
            float hb = __uint_as_float(hp & 0xFFFF0000u);
            uint32_t mp; CVT_BF16X2(mp, a - ha, b - hb);
            hi[c2] = hp; mi[c2] = mp;
        }
        hi[14] = hi[15] = mi[14] = mi[15] = 0;

        // Store this point's feature row (row = lane), 80B stride
        {
            uint32_t* rh = &sFH[w][lane * ROWU];
            uint32_t* rm = &sFM[w][lane * ROWU];
            *(uint4*)(rh + 0)  = make_uint4(hi[0], hi[1], hi[2], hi[3]);
            *(uint4*)(rh + 4)  = make_uint4(hi[4], hi[5], hi[6], hi[7]);
            *(uint4*)(rh + 8)  = make_uint4(hi[8], hi[9], hi[10], hi[11]);
            *(uint4*)(rh + 12) = make_uint4(hi[12], hi[13], hi[14], hi[15]);
            *(uint4*)(rm + 0)  = make_uint4(mi[0], mi[1], mi[2], mi[3]);
            *(uint4*)(rm + 4)  = make_uint4(mi[4], mi[5], mi[6], mi[7]);
            *(uint4*)(rm + 8)  = make_uint4(mi[8], mi[9], mi[10], mi[11]);
            *(uint4*)(rm + 12) = make_uint4(mi[12], mi[13], mi[14], mi[15]);
        }
        __syncwarp();

        // Two m16 tiles of 16 points each
        #pragma unroll
        for (int mt = 0; mt < 2; mt++) {
            int rowl = mt * 16 + (lane & 15);
            uint32_t aoff = (uint32_t)(rowl * 80 + ((lane >> 4) & 1) * 16);
            uint32_t ah[8], am[8];
            ldmatrix_x4(ah[0], ah[1], ah[2], ah[3], fhB + aoff);
            ldmatrix_x4(ah[4], ah[5], ah[6], ah[7], fhB + aoff + 32);
            ldmatrix_x4(am[0], am[1], am[2], am[3], fmB + aoff);
            ldmatrix_x4(am[4], am[5], am[6], am[7], fmB + aoff + 32);

            float C[4][4];
            #pragma unroll
            for (int nc = 0; nc < 4; nc++)
                { C[nc][0] = C[nc][1] = C[nc][2] = C[nc][3] = 0.0f; }

            #pragma unroll
            for (int nc = 0; nc < 4; nc++) {
                #pragma unroll
                for (int ks = 0; ks < 2; ks++) {
                    mma16816(C[nc], ah + ks * 4, bh[nc][ks][0], bh[nc][ks][1]);
                    mma16816(C[nc], ah + ks * 4, bm[nc][ks][0], bm[nc][ks][1]);
                    mma16816(C[nc], am + ks * 4, bh[nc][ks][0], bh[nc][ks][1]);
                }
            }

            // Epilogue: relu(h + b1) dot W2, reduced across the 4-lane group
            float s0 = 0.0f, s1 = 0.0f;
            #pragma unroll
            for (int nc = 0; nc < 4; nc++) {
                s0 = fmaf(fmaxf(C[nc][0] + bw0[nc].x, 0.0f), bw0[nc].y, s0);
                s0 = fmaf(fmaxf(C[nc][1] + bw1[nc].x, 0.0f), bw1[nc].y, s0);
                s1 = fmaf(fmaxf(C[nc][2] + bw0[nc].x, 0.0f), bw0[nc].y, s1);
                s1 = fmaf(fmaxf(C[nc][3] + bw1[nc].x, 0.0f), bw1[nc].y, s1);
            }
            s0 += __shfl_xor_sync(0xFFFFFFFFu, s0, 1);
            s0 += __shfl_xor_sync(0xFFFFFFFFu, s0, 2);
            s1 += __shfl_xor_sync(0xFFFFFFFFu, s1, 1);
            s1 += __shfl_xor_sync(0xFFFFFFFFu, s1, 2);
            if (t4 == 0) {
                long long q0 = pbase + mt * 16 + g4;
                long long q1 = q0 + 8;
                if (q0 < N) out[q0] = fmaxf(s0 + b2v, 0.0f);
                if (q1 < N) out[q1] = fmaxf(s1 + b2v, 0.0f);
            }
        }
        __syncwarp();
    }
}

extern "C" void kernel_launch(void* const* d_in, const int* in_sizes, int n_in,
                              void* d_out, int out_size) {
    const float* x  = (const float*)d_in[0];
    const float* W1 = (const float*)d_in[1];
    const float* b1 = (const float*)d_in[2];
    const float* W2 = (const float*)d_in[3];
    const float* b2 = (const float*)d_in[4];
    float* out = (float*)d_out;

    long long N = in_sizes[0] / 3;
    long long per_block = (long long)ITER * TPB;   // 1024 points per block
    int blocks = (int)((N + per_block - 1) / per_block);
    nerf_hmma_kernel<<<blocks, TPB>>>(x, W1, b1, W2, b2, out, N);
}